// round 1
// baseline (speedup 1.0000x reference)
#include <cuda_runtime.h>
#include <cuda_bf16.h>
#include <math.h>

// Problem constants: B=2, T=2048, C=1024, H=16, D=64
#define TB   2
#define TT   2048
#define TC   1024
#define TH   16
#define TD   64
#define TM_  (TB*TT)          // 4096 rows total
#define C3   (3*TC)           // 3072

// ---------------------------------------------------------------------------
// Scratch (no allocations allowed -> __device__ globals)
// ---------------------------------------------------------------------------
__device__ float g_h1  [TM_ * TC];        // ln1(x)
__device__ float g_qkv [TM_ * C3];        // qkv
__device__ float g_att [TM_ * TC];        // attention output
__device__ float g_x1  [TM_ * TC];        // x + attn_proj
__device__ float g_h2  [TM_ * TC];        // ln2(x1)
__device__ float g_fc  [TM_ * 4 * TC];    // gelu(fc)

// ---------------------------------------------------------------------------
// Block reduce
// ---------------------------------------------------------------------------
__device__ __forceinline__ float blockReduceSum(float v) {
    __shared__ float sh[32];
    int lane = threadIdx.x & 31;
    #pragma unroll
    for (int o = 16; o > 0; o >>= 1) v += __shfl_xor_sync(0xffffffffu, v, o);
    __syncthreads();                     // protect sh vs previous call's readers
    if (lane == 0) sh[threadIdx.x >> 5] = v;
    __syncthreads();
    float t = (lane < 8) ? sh[lane] : 0.f;   // 256 threads = 8 warps
    #pragma unroll
    for (int o = 4; o > 0; o >>= 1) t += __shfl_xor_sync(0xffffffffu, t, o);
    return __shfl_sync(0xffffffffu, t, 0);
}

// ---------------------------------------------------------------------------
// LayerNorm: one block per row of 1024, 256 threads * float4
// ---------------------------------------------------------------------------
__global__ __launch_bounds__(256) void layernorm_kernel(
    const float* __restrict__ x, const float* __restrict__ g,
    const float* __restrict__ b, float* __restrict__ out)
{
    int row = blockIdx.x;
    const float4* xr = reinterpret_cast<const float4*>(x + (size_t)row * TC);
    float4 v = xr[threadIdx.x];
    float mean = blockReduceSum(v.x + v.y + v.z + v.w) * (1.f / TC);
    float dx = v.x - mean, dy = v.y - mean, dz = v.z - mean, dw = v.w - mean;
    float var = blockReduceSum(dx*dx + dy*dy + dz*dz + dw*dw) * (1.f / TC);
    float rstd = rsqrtf(var + 1e-5f);
    float4 gv = reinterpret_cast<const float4*>(g)[threadIdx.x];
    float4 bv = reinterpret_cast<const float4*>(b)[threadIdx.x];
    float4 o;
    o.x = dx * rstd * gv.x + bv.x;
    o.y = dy * rstd * gv.y + bv.y;
    o.z = dz * rstd * gv.z + bv.z;
    o.w = dw * rstd * gv.w + bv.w;
    reinterpret_cast<float4*>(out + (size_t)row * TC)[threadIdx.x] = o;
}

// ---------------------------------------------------------------------------
// SGEMM: C[M,N] = A[M,K] @ B[K,N] + bias, optional GELU / residual epilogue.
// BM=BN=128, BK=8, 256 threads, 8x8 register tile per thread.
// All dims here are multiples of the tiles -> no bounds checks.
// EPI: 0 = bias, 1 = bias+exact GELU, 2 = bias+residual add
// ---------------------------------------------------------------------------
template <int EPI>
__global__ __launch_bounds__(256) void sgemm_kernel(
    const float* __restrict__ A, const float* __restrict__ B,
    const float* __restrict__ bias, const float* __restrict__ res,
    float* __restrict__ C, int M, int N, int K)
{
    constexpr int BM = 128, BN = 128, BK = 8, TMr = 8, TNr = 8;
    __shared__ float As[BK][BM];
    __shared__ float Bs[BK][BN];

    int tid  = threadIdx.x;
    int brow = blockIdx.y * BM;
    int bcol = blockIdx.x * BN;

    int arow = tid >> 1;            // 0..127
    int acol = (tid & 1) * 4;       // 0 or 4
    int brw  = tid >> 5;            // 0..7
    int bcl  = (tid & 31) * 4;      // 0..124

    const float* Ap = A + (size_t)(brow + arow) * K + acol;
    const float* Bp = B + (size_t)brw * N + bcol + bcl;

    float acc[TMr][TNr];
    #pragma unroll
    for (int i = 0; i < TMr; i++)
        #pragma unroll
        for (int j = 0; j < TNr; j++) acc[i][j] = 0.f;

    int tr = (tid >> 4) * TMr;      // 0..120
    int tc = (tid & 15) * TNr;      // 0..120

    for (int k0 = 0; k0 < K; k0 += BK) {
        float4 a4 = *reinterpret_cast<const float4*>(Ap + k0);
        As[acol + 0][arow] = a4.x;
        As[acol + 1][arow] = a4.y;
        As[acol + 2][arow] = a4.z;
        As[acol + 3][arow] = a4.w;
        float4 b4 = *reinterpret_cast<const float4*>(Bp + (size_t)k0 * N);
        *reinterpret_cast<float4*>(&Bs[brw][bcl]) = b4;
        __syncthreads();

        #pragma unroll
        for (int kk = 0; kk < BK; kk++) {
            float ra[TMr], rb[TNr];
            float4 t0 = *reinterpret_cast<const float4*>(&As[kk][tr]);
            float4 t1 = *reinterpret_cast<const float4*>(&As[kk][tr + 4]);
            ra[0]=t0.x; ra[1]=t0.y; ra[2]=t0.z; ra[3]=t0.w;
            ra[4]=t1.x; ra[5]=t1.y; ra[6]=t1.z; ra[7]=t1.w;
            float4 u0 = *reinterpret_cast<const float4*>(&Bs[kk][tc]);
            float4 u1 = *reinterpret_cast<const float4*>(&Bs[kk][tc + 4]);
            rb[0]=u0.x; rb[1]=u0.y; rb[2]=u0.z; rb[3]=u0.w;
            rb[4]=u1.x; rb[5]=u1.y; rb[6]=u1.z; rb[7]=u1.w;
            #pragma unroll
            for (int i = 0; i < TMr; i++)
                #pragma unroll
                for (int j = 0; j < TNr; j++)
                    acc[i][j] += ra[i] * rb[j];
        }
        __syncthreads();
    }

    int grow = brow + tr;
    int gcol = bcol + tc;
    #pragma unroll
    for (int i = 0; i < TMr; i++) {
        size_t base = (size_t)(grow + i) * N + gcol;
        #pragma unroll
        for (int j = 0; j < TNr; j++) {
            float v = acc[i][j] + bias[gcol + j];
            if (EPI == 1) {
                v = 0.5f * v * (1.0f + erff(v * 0.70710678118654752440f));
            } else if (EPI == 2) {
                v += res[base + j];
            }
            C[base + j] = v;
        }
    }
}

// ---------------------------------------------------------------------------
// Causal flash attention, fp32.
// Grid: (T/64, B*H). Block: 64 threads, thread t owns q-row qt*64+t.
// K/V tiles [64x64] staged in smem, read back as broadcast float4 (conflict-free).
// Streaming (online) softmax is thread-local and exact.
// smem: 3 * 64*64*4 = 48 KB (static limit).
// ---------------------------------------------------------------------------
__global__ __launch_bounds__(64) void attn_kernel(
    const float* __restrict__ qkv, float* __restrict__ out)
{
    __shared__ float Ks[64][64];
    __shared__ float Vs[64][64];
    __shared__ float Ss[64][64];   // always indexed [j][lane] -> conflict-free

    int qt = blockIdx.x;
    int b  = blockIdx.y >> 4;
    int h  = blockIdx.y & 15;
    int t  = threadIdx.x;
    int qrow = qt * 64 + t;

    // load this thread's q row into registers
    const float* qp = qkv + (size_t)(b * TT + qrow) * C3 + h * TD;
    float q[64];
    #pragma unroll
    for (int d4 = 0; d4 < 16; d4++) {
        float4 v = reinterpret_cast<const float4*>(qp)[d4];
        q[4*d4] = v.x; q[4*d4+1] = v.y; q[4*d4+2] = v.z; q[4*d4+3] = v.w;
    }

    float O[64];
    #pragma unroll
    for (int d = 0; d < 64; d++) O[d] = 0.f;
    float m = -1e30f, l = 0.f;

    for (int kt = 0; kt <= qt; kt++) {
        __syncthreads();   // smem tile reuse
        const float* kb = qkv + (size_t)(b * TT + kt * 64) * C3 + TC + h * TD;
        const float* vb = kb + TC;
        #pragma unroll 4
        for (int r = 0; r < 64; r++) {
            Ks[r][t] = kb[(size_t)r * C3 + t];
            Vs[r][t] = vb[(size_t)r * C3 + t];
        }
        __syncthreads();

        int jlim = (kt == qt) ? t : 63;
        float tmax = -1e30f;
        for (int j = 0; j <= jlim; j++) {
            const float4* kr = reinterpret_cast<const float4*>(&Ks[j][0]);
            float s0 = 0.f, s1 = 0.f, s2 = 0.f, s3 = 0.f;  // break FMA dep chain
            #pragma unroll
            for (int d4 = 0; d4 < 16; d4 += 4) {
                float4 k0 = kr[d4], k1 = kr[d4+1], k2 = kr[d4+2], k3 = kr[d4+3];
                s0 += q[4*d4   ]*k0.x + q[4*d4+1 ]*k0.y + q[4*d4+2 ]*k0.z + q[4*d4+3 ]*k0.w;
                s1 += q[4*d4+4 ]*k1.x + q[4*d4+5 ]*k1.y + q[4*d4+6 ]*k1.z + q[4*d4+7 ]*k1.w;
                s2 += q[4*d4+8 ]*k2.x + q[4*d4+9 ]*k2.y + q[4*d4+10]*k2.z + q[4*d4+11]*k2.w;
                s3 += q[4*d4+12]*k3.x + q[4*d4+13]*k3.y + q[4*d4+14]*k3.z + q[4*d4+15]*k3.w;
            }
            float s = ((s0 + s1) + (s2 + s3)) * 0.03125f;   // * C^-0.5
            Ss[j][t] = s;
            tmax = fmaxf(tmax, s);
        }

        float mnew = fmaxf(m, tmax);
        float corr = __expf(m - mnew);
        l *= corr;
        #pragma unroll
        for (int d = 0; d < 64; d++) O[d] *= corr;

        for (int j = 0; j <= jlim; j++) {
            float p = __expf(Ss[j][t] - mnew);
            l += p;
            const float4* vr = reinterpret_cast<const float4*>(&Vs[j][0]);
            #pragma unroll
            for (int d4 = 0; d4 < 16; d4++) {
                float4 vv = vr[d4];
                O[4*d4  ] += p * vv.x;
                O[4*d4+1] += p * vv.y;
                O[4*d4+2] += p * vv.z;
                O[4*d4+3] += p * vv.w;
            }
        }
        m = mnew;
    }

    float inv = 1.f / l;
    float* op = out + (size_t)(b * TT + qrow) * TC + h * TD;
    #pragma unroll
    for (int d4 = 0; d4 < 16; d4++) {
        float4 o;
        o.x = O[4*d4  ] * inv;
        o.y = O[4*d4+1] * inv;
        o.z = O[4*d4+2] * inv;
        o.w = O[4*d4+3] * inv;
        reinterpret_cast<float4*>(op)[d4] = o;
    }
}

// ---------------------------------------------------------------------------
// Launch
// ---------------------------------------------------------------------------
extern "C" void kernel_launch(void* const* d_in, const int* in_sizes, int n_in,
                              void* d_out, int out_size)
{
    const float* x           = (const float*)d_in[0];
    const float* ln1_g       = (const float*)d_in[1];
    const float* ln1_b       = (const float*)d_in[2];
    const float* w_qkv       = (const float*)d_in[3];
    const float* b_qkv       = (const float*)d_in[4];
    const float* w_attn_proj = (const float*)d_in[5];
    const float* b_attn_proj = (const float*)d_in[6];
    const float* ln2_g       = (const float*)d_in[7];
    const float* ln2_b       = (const float*)d_in[8];
    const float* w_fc        = (const float*)d_in[9];
    const float* b_fc        = (const float*)d_in[10];
    const float* w_out       = (const float*)d_in[11];
    const float* b_out       = (const float*)d_in[12];

    float *h1, *qkv, *att, *x1, *h2, *fc;
    cudaGetSymbolAddress((void**)&h1,  g_h1);
    cudaGetSymbolAddress((void**)&qkv, g_qkv);
    cudaGetSymbolAddress((void**)&att, g_att);
    cudaGetSymbolAddress((void**)&x1,  g_x1);
    cudaGetSymbolAddress((void**)&h2,  g_h2);
    cudaGetSymbolAddress((void**)&fc,  g_fc);

    // 1) ln1(x)
    layernorm_kernel<<<TM_, 256>>>(x, ln1_g, ln1_b, h1);
    // 2) qkv = h1 @ w_qkv + b_qkv           [4096,3072]
    sgemm_kernel<0><<<dim3(C3 / 128, TM_ / 128), 256>>>(
        h1, w_qkv, b_qkv, nullptr, qkv, TM_, C3, TC);
    // 3) causal attention
    attn_kernel<<<dim3(TT / 64, TB * TH), 64>>>(qkv, att);
    // 4) x1 = x + att @ w_attn_proj + b     [4096,1024]
    sgemm_kernel<2><<<dim3(TC / 128, TM_ / 128), 256>>>(
        att, w_attn_proj, b_attn_proj, x, x1, TM_, TC, TC);
    // 5) ln2(x1)
    layernorm_kernel<<<TM_, 256>>>(x1, ln2_g, ln2_b, h2);
    // 6) fc = gelu(h2 @ w_fc + b_fc)        [4096,4096]
    sgemm_kernel<1><<<dim3(4 * TC / 128, TM_ / 128), 256>>>(
        h2, w_fc, b_fc, nullptr, fc, TM_, 4 * TC, TC);
    // 7) out = x1 + fc @ w_out + b_out      [4096,1024]
    sgemm_kernel<2><<<dim3(TC / 128, TM_ / 128), 256>>>(
        fc, w_out, b_out, x1, (float*)d_out, TM_, TC, 4 * TC);
}

// round 3
// speedup vs baseline: 2.0085x; 2.0085x over previous
#include <cuda_runtime.h>
#include <cuda_bf16.h>
#include <math.h>
#include <stdint.h>

// Problem constants: B=2, T=2048, C=1024, H=16, D=64
#define TB   2
#define TT   2048
#define TC   1024
#define TH   16
#define TD   64
#define TM_  (TB*TT)          // 4096 rows total
#define C3   (3*TC)           // 3072
#define C4   (4*TC)           // 4096

// ---------------------------------------------------------------------------
// Scratch (no allocations allowed -> __device__ globals)
// ---------------------------------------------------------------------------
__device__ float g_h1   [TM_ * TC];       // ln1(x)           (tf32-rounded)
__device__ float g_qkv  [TM_ * C3];       // qkv              (full fp32)
__device__ float g_att  [TM_ * TC];       // attention output (tf32-rounded)
__device__ float g_x1   [TM_ * TC];       // x + attn_proj    (full fp32)
__device__ float g_h2   [TM_ * TC];       // ln2(x1)          (tf32-rounded)
__device__ float g_fc   [TM_ * C4];       // gelu(fc)         (tf32-rounded)
// transposed weights (K-major, [N][K], tf32-rounded)
__device__ float g_wqkvT[C3 * TC];
__device__ float g_wapT [TC * TC];
__device__ float g_wfcT [C4 * TC];
__device__ float g_woutT[TC * C4];

// ---------------------------------------------------------------------------
// Helpers
// ---------------------------------------------------------------------------
__device__ __forceinline__ float tf32r(float f) {
    uint32_t r;
    asm("cvt.rna.tf32.f32 %0, %1;" : "=r"(r) : "f"(f));
    return __uint_as_float(r);
}
__device__ __forceinline__ uint32_t smem_u32(const void* p) {
    uint32_t a;
    asm("{ .reg .u64 t; cvta.to.shared.u64 t, %1; cvt.u32.u64 %0, t; }"
        : "=r"(a) : "l"(p));
    return a;
}
__device__ __forceinline__ void cp_async16(uint32_t dst, const void* src) {
    asm volatile("cp.async.cg.shared.global [%0], [%1], 16;"
                 :: "r"(dst), "l"(src) : "memory");
}
#define CP_COMMIT() asm volatile("cp.async.commit_group;" ::: "memory")
#define CP_WAIT1()  asm volatile("cp.async.wait_group 1;" ::: "memory")

__device__ __forceinline__ void mma_tf32(float* d, const uint32_t* a, const uint32_t* b) {
    asm volatile(
        "mma.sync.aligned.m16n8k8.row.col.f32.tf32.tf32.f32 "
        "{%0,%1,%2,%3}, {%4,%5,%6,%7}, {%8,%9}, {%0,%1,%2,%3};"
        : "+f"(d[0]), "+f"(d[1]), "+f"(d[2]), "+f"(d[3])
        : "r"(a[0]), "r"(a[1]), "r"(a[2]), "r"(a[3]), "r"(b[0]), "r"(b[1]));
}

// ---------------------------------------------------------------------------
// Weight transpose + tf32 round: Wt[n][k] = tf32(W[k][n])
// ---------------------------------------------------------------------------
__global__ __launch_bounds__(256) void transpose_kernel(
    const float* __restrict__ W, float* __restrict__ Wt, int K, int N)
{
    __shared__ float tile[32][33];
    int k0 = blockIdx.y * 32, n0 = blockIdx.x * 32;
    int tx = threadIdx.x, ty = threadIdx.y;   // block (32,8)
    #pragma unroll
    for (int i = ty; i < 32; i += 8)
        tile[i][tx] = W[(size_t)(k0 + i) * N + n0 + tx];
    __syncthreads();
    #pragma unroll
    for (int i = ty; i < 32; i += 8)
        Wt[(size_t)(n0 + i) * K + k0 + tx] = tf32r(tile[tx][i]);
}

// ---------------------------------------------------------------------------
// Tensor-core tf32 GEMM: C[M,N] = A[M,K] @ Bt[N,K]^T + bias (+GELU / +residual)
// BM=BN=128, BK=32. 256 threads = 8 warps in 4(m) x 2(n); warp tile 32x64.
// mma.sync m16n8k8 tf32. 3-stage cp.async pipeline.
// SMEM per stage: A[128][36] + B[128][36] floats (stride-36 pad: conflict-free)
// EPI: 0 = bias, 1 = bias + exact GELU + tf32 round, 2 = bias + residual
// ---------------------------------------------------------------------------
#define SSTRIDE   36
#define BUF_FL    (128 * SSTRIDE)        // floats per matrix per stage
#define STAGE_FL  (2 * BUF_FL)           // A + B
#define NSTAGE    3
#define G_SMEM    (NSTAGE * STAGE_FL * 4)  // 110592 bytes

template <int EPI>
__global__ __launch_bounds__(256) void mma_gemm(
    const float* __restrict__ A, const float* __restrict__ Bt,
    const float* __restrict__ bias, const float* __restrict__ res,
    float* __restrict__ C, int M, int N, int K)
{
    extern __shared__ float sh[];
    uint32_t sbase = smem_u32(sh);

    int tid  = threadIdx.x;
    int wid  = tid >> 5;
    int lane = tid & 31;
    int g    = lane >> 2;     // 0..7
    int t    = lane & 3;      // 0..3
    int brow = blockIdx.y * 128;
    int bcol = blockIdx.x * 128;
    int m0   = (wid >> 1) * 32;   // warp m offset in tile
    int n0   = (wid & 1) * 64;    // warp n offset in tile

    const float* Ag = A  + (size_t)brow * K;
    const float* Bg = Bt + (size_t)bcol * K;

    int NC = K >> 5;   // k-chunks of 32

    // ---- async stage loader: chunk kc -> stage kc % 3 ----
    auto issue = [&](int kc) {
        if (kc < NC) {
            int k0 = kc << 5;
            uint32_t buf = sbase + (uint32_t)(kc % NSTAGE) * (STAGE_FL * 4);
            #pragma unroll
            for (int i = 0; i < 4; i++) {
                int idx = tid + (i << 8);      // 0..1023
                int row = idx >> 3;            // 0..127
                int c   = idx & 7;             // 16B chunk in 128B row
                uint32_t so = (uint32_t)(row * SSTRIDE + c * 4) * 4;
                cp_async16(buf + so,              Ag + (size_t)row * K + k0 + c * 4);
                cp_async16(buf + BUF_FL * 4 + so, Bg + (size_t)row * K + k0 + c * 4);
            }
        }
        CP_COMMIT();
    };

    float acc[2][8][4];
    #pragma unroll
    for (int i = 0; i < 2; i++)
        #pragma unroll
        for (int j = 0; j < 8; j++)
            #pragma unroll
            for (int q = 0; q < 4; q++) acc[i][j][q] = 0.f;

    issue(0);
    issue(1);

    for (int kc = 0; kc < NC; kc++) {
        CP_WAIT1();            // stage kc complete
        __syncthreads();
        issue(kc + 2);         // overwrites stage read at iter kc-1 (safe post-sync)

        const float* As = sh + (kc % NSTAGE) * STAGE_FL;
        const float* Bs = As + BUF_FL;

        #pragma unroll
        for (int ks = 0; ks < 4; ks++) {     // k-steps of 8
            uint32_t a[2][4];
            #pragma unroll
            for (int i = 0; i < 2; i++) {
                const float* p = As + (m0 + i * 16 + g) * SSTRIDE + ks * 8 + t;
                a[i][0] = __float_as_uint(p[0]);
                a[i][1] = __float_as_uint(p[8 * SSTRIDE]);
                a[i][2] = __float_as_uint(p[4]);
                a[i][3] = __float_as_uint(p[8 * SSTRIDE + 4]);
            }
            uint32_t b[8][2];
            #pragma unroll
            for (int j = 0; j < 8; j++) {
                const float* p = Bs + (n0 + j * 8 + g) * SSTRIDE + ks * 8 + t;
                b[j][0] = __float_as_uint(p[0]);
                b[j][1] = __float_as_uint(p[4]);
            }
            #pragma unroll
            for (int i = 0; i < 2; i++)
                #pragma unroll
                for (int j = 0; j < 8; j++)
                    mma_tf32(acc[i][j], a[i], b[j]);
        }
    }

    // ---- epilogue ----
    #pragma unroll
    for (int i = 0; i < 2; i++) {
        int r0 = brow + m0 + i * 16 + g;
        int r1 = r0 + 8;
        #pragma unroll
        for (int j = 0; j < 8; j++) {
            int c0 = bcol + n0 + j * 8 + 2 * t;
            float bx = bias[c0], by = bias[c0 + 1];
            float v0 = acc[i][j][0] + bx;
            float v1 = acc[i][j][1] + by;
            float v2 = acc[i][j][2] + bx;
            float v3 = acc[i][j][3] + by;
            if (EPI == 1) {
                v0 = tf32r(0.5f * v0 * (1.0f + erff(v0 * 0.70710678118654752440f)));
                v1 = tf32r(0.5f * v1 * (1.0f + erff(v1 * 0.70710678118654752440f)));
                v2 = tf32r(0.5f * v2 * (1.0f + erff(v2 * 0.70710678118654752440f)));
                v3 = tf32r(0.5f * v3 * (1.0f + erff(v3 * 0.70710678118654752440f)));
            } else if (EPI == 2) {
                const float2 ra = *reinterpret_cast<const float2*>(res + (size_t)r0 * N + c0);
                const float2 rb = *reinterpret_cast<const float2*>(res + (size_t)r1 * N + c0);
                v0 += ra.x; v1 += ra.y; v2 += rb.x; v3 += rb.y;
            }
            *reinterpret_cast<float2*>(C + (size_t)r0 * N + c0) = make_float2(v0, v1);
            *reinterpret_cast<float2*>(C + (size_t)r1 * N + c0) = make_float2(v2, v3);
        }
    }
}

// ---------------------------------------------------------------------------
// Block reduce (for LayerNorm)
// ---------------------------------------------------------------------------
__device__ __forceinline__ float blockReduceSum(float v) {
    __shared__ float sh[32];
    int lane = threadIdx.x & 31;
    #pragma unroll
    for (int o = 16; o > 0; o >>= 1) v += __shfl_xor_sync(0xffffffffu, v, o);
    __syncthreads();
    if (lane == 0) sh[threadIdx.x >> 5] = v;
    __syncthreads();
    float t = (lane < 8) ? sh[lane] : 0.f;
    #pragma unroll
    for (int o = 4; o > 0; o >>= 1) t += __shfl_xor_sync(0xffffffffu, t, o);
    return __shfl_sync(0xffffffffu, t, 0);
}

// ---------------------------------------------------------------------------
// LayerNorm (output tf32-rounded: it is always a GEMM A-operand)
// ---------------------------------------------------------------------------
__global__ __launch_bounds__(256) void layernorm_kernel(
    const float* __restrict__ x, const float* __restrict__ g,
    const float* __restrict__ b, float* __restrict__ out)
{
    int row = blockIdx.x;
    const float4* xr = reinterpret_cast<const float4*>(x + (size_t)row * TC);
    float4 v = xr[threadIdx.x];
    float mean = blockReduceSum(v.x + v.y + v.z + v.w) * (1.f / TC);
    float dx = v.x - mean, dy = v.y - mean, dz = v.z - mean, dw = v.w - mean;
    float var = blockReduceSum(dx*dx + dy*dy + dz*dz + dw*dw) * (1.f / TC);
    float rstd = rsqrtf(var + 1e-5f);
    float4 gv = reinterpret_cast<const float4*>(g)[threadIdx.x];
    float4 bv = reinterpret_cast<const float4*>(b)[threadIdx.x];
    float4 o;
    o.x = tf32r(dx * rstd * gv.x + bv.x);
    o.y = tf32r(dy * rstd * gv.y + bv.y);
    o.z = tf32r(dz * rstd * gv.z + bv.z);
    o.w = tf32r(dw * rstd * gv.w + bv.w);
    reinterpret_cast<float4*>(out + (size_t)row * TC)[threadIdx.x] = o;
}

// ---------------------------------------------------------------------------
// Causal flash attention, fp32 (output tf32-rounded: feeds proj GEMM).
// ---------------------------------------------------------------------------
__global__ __launch_bounds__(64) void attn_kernel(
    const float* __restrict__ qkv, float* __restrict__ out)
{
    __shared__ float Ks[64][64];
    __shared__ float Vs[64][64];
    __shared__ float Ss[64][64];

    int qt = blockIdx.x;
    int b  = blockIdx.y >> 4;
    int h  = blockIdx.y & 15;
    int t  = threadIdx.x;
    int qrow = qt * 64 + t;

    const float* qp = qkv + (size_t)(b * TT + qrow) * C3 + h * TD;
    float q[64];
    #pragma unroll
    for (int d4 = 0; d4 < 16; d4++) {
        float4 v = reinterpret_cast<const float4*>(qp)[d4];
        q[4*d4] = v.x; q[4*d4+1] = v.y; q[4*d4+2] = v.z; q[4*d4+3] = v.w;
    }

    float O[64];
    #pragma unroll
    for (int d = 0; d < 64; d++) O[d] = 0.f;
    float m = -1e30f, l = 0.f;

    for (int kt = 0; kt <= qt; kt++) {
        __syncthreads();
        const float* kb = qkv + (size_t)(b * TT + kt * 64) * C3 + TC + h * TD;
        const float* vb = kb + TC;
        #pragma unroll 4
        for (int r = 0; r < 64; r++) {
            Ks[r][t] = kb[(size_t)r * C3 + t];
            Vs[r][t] = vb[(size_t)r * C3 + t];
        }
        __syncthreads();

        int jlim = (kt == qt) ? t : 63;
        float tmax = -1e30f;
        for (int j = 0; j <= jlim; j++) {
            const float4* kr = reinterpret_cast<const float4*>(&Ks[j][0]);
            float s0 = 0.f, s1 = 0.f, s2 = 0.f, s3 = 0.f;
            #pragma unroll
            for (int d4 = 0; d4 < 16; d4 += 4) {
                float4 k0 = kr[d4], k1 = kr[d4+1], k2 = kr[d4+2], k3 = kr[d4+3];
                s0 += q[4*d4   ]*k0.x + q[4*d4+1 ]*k0.y + q[4*d4+2 ]*k0.z + q[4*d4+3 ]*k0.w;
                s1 += q[4*d4+4 ]*k1.x + q[4*d4+5 ]*k1.y + q[4*d4+6 ]*k1.z + q[4*d4+7 ]*k1.w;
                s2 += q[4*d4+8 ]*k2.x + q[4*d4+9 ]*k2.y + q[4*d4+10]*k2.z + q[4*d4+11]*k2.w;
                s3 += q[4*d4+12]*k3.x + q[4*d4+13]*k3.y + q[4*d4+14]*k3.z + q[4*d4+15]*k3.w;
            }
            float s = ((s0 + s1) + (s2 + s3)) * 0.03125f;
            Ss[j][t] = s;
            tmax = fmaxf(tmax, s);
        }

        float mnew = fmaxf(m, tmax);
        float corr = __expf(m - mnew);
        l *= corr;
        #pragma unroll
        for (int d = 0; d < 64; d++) O[d] *= corr;

        for (int j = 0; j <= jlim; j++) {
            float p = __expf(Ss[j][t] - mnew);
            l += p;
            const float4* vr = reinterpret_cast<const float4*>(&Vs[j][0]);
            #pragma unroll
            for (int d4 = 0; d4 < 16; d4++) {
                float4 vv = vr[d4];
                O[4*d4  ] += p * vv.x;
                O[4*d4+1] += p * vv.y;
                O[4*d4+2] += p * vv.z;
                O[4*d4+3] += p * vv.w;
            }
        }
        m = mnew;
    }

    float inv = 1.f / l;
    float* op = out + (size_t)(b * TT + qrow) * TC + h * TD;
    #pragma unroll
    for (int d4 = 0; d4 < 16; d4++) {
        float4 o;
        o.x = tf32r(O[4*d4  ] * inv);
        o.y = tf32r(O[4*d4+1] * inv);
        o.z = tf32r(O[4*d4+2] * inv);
        o.w = tf32r(O[4*d4+3] * inv);
        reinterpret_cast<float4*>(op)[d4] = o;
    }
}

// ---------------------------------------------------------------------------
// Launch
// ---------------------------------------------------------------------------
extern "C" void kernel_launch(void* const* d_in, const int* in_sizes, int n_in,
                              void* d_out, int out_size)
{
    const float* x           = (const float*)d_in[0];
    const float* ln1_g       = (const float*)d_in[1];
    const float* ln1_b       = (const float*)d_in[2];
    const float* w_qkv       = (const float*)d_in[3];
    const float* b_qkv       = (const float*)d_in[4];
    const float* w_attn_proj = (const float*)d_in[5];
    const float* b_attn_proj = (const float*)d_in[6];
    const float* ln2_g       = (const float*)d_in[7];
    const float* ln2_b       = (const float*)d_in[8];
    const float* w_fc        = (const float*)d_in[9];
    const float* b_fc        = (const float*)d_in[10];
    const float* w_out       = (const float*)d_in[11];
    const float* b_out       = (const float*)d_in[12];

    float *h1, *qkv, *att, *x1, *h2, *fc, *wqkvT, *wapT, *wfcT, *woutT;
    cudaGetSymbolAddress((void**)&h1,    g_h1);
    cudaGetSymbolAddress((void**)&qkv,   g_qkv);
    cudaGetSymbolAddress((void**)&att,   g_att);
    cudaGetSymbolAddress((void**)&x1,    g_x1);
    cudaGetSymbolAddress((void**)&h2,    g_h2);
    cudaGetSymbolAddress((void**)&fc,    g_fc);
    cudaGetSymbolAddress((void**)&wqkvT, g_wqkvT);
    cudaGetSymbolAddress((void**)&wapT,  g_wapT);
    cudaGetSymbolAddress((void**)&wfcT,  g_wfcT);
    cudaGetSymbolAddress((void**)&woutT, g_woutT);

    cudaFuncSetAttribute(mma_gemm<0>, cudaFuncAttributeMaxDynamicSharedMemorySize, G_SMEM);
    cudaFuncSetAttribute(mma_gemm<1>, cudaFuncAttributeMaxDynamicSharedMemorySize, G_SMEM);
    cudaFuncSetAttribute(mma_gemm<2>, cudaFuncAttributeMaxDynamicSharedMemorySize, G_SMEM);

    // 0) transpose + tf32-round weights to K-major
    transpose_kernel<<<dim3(C3 / 32, TC / 32), dim3(32, 8)>>>(w_qkv,       wqkvT, TC, C3);
    transpose_kernel<<<dim3(TC / 32, TC / 32), dim3(32, 8)>>>(w_attn_proj, wapT,  TC, TC);
    transpose_kernel<<<dim3(C4 / 32, TC / 32), dim3(32, 8)>>>(w_fc,        wfcT,  TC, C4);
    transpose_kernel<<<dim3(TC / 32, C4 / 32), dim3(32, 8)>>>(w_out,       woutT, C4, TC);

    // 1) ln1(x)
    layernorm_kernel<<<TM_, 256>>>(x, ln1_g, ln1_b, h1);
    // 2) qkv = h1 @ w_qkv + b_qkv           [4096,3072] K=1024
    mma_gemm<0><<<dim3(C3 / 128, TM_ / 128), 256, G_SMEM>>>(
        h1, wqkvT, b_qkv, nullptr, qkv, TM_, C3, TC);
    // 3) causal attention
    attn_kernel<<<dim3(TT / 64, TB * TH), 64>>>(qkv, att);
    // 4) x1 = x + att @ w_attn_proj + b     [4096,1024] K=1024
    mma_gemm<2><<<dim3(TC / 128, TM_ / 128), 256, G_SMEM>>>(
        att, wapT, b_attn_proj, x, x1, TM_, TC, TC);
    // 5) ln2(x1)
    layernorm_kernel<<<TM_, 256>>>(x1, ln2_g, ln2_b, h2);
    // 6) fc = gelu(h2 @ w_fc + b_fc)        [4096,4096] K=1024
    mma_gemm<1><<<dim3(C4 / 128, TM_ / 128), 256, G_SMEM>>>(
        h2, wfcT, b_fc, nullptr, fc, TM_, C4, TC);
    // 7) out = x1 + fc @ w_out + b_out      [4096,1024] K=4096
    mma_gemm<2><<<dim3(TC / 128, TM_ / 128), 256, G_SMEM>>>(
        fc, woutT, b_out, x1, (float*)d_out, TM_, TC, C4);
}

// round 4
// speedup vs baseline: 5.8411x; 2.9081x over previous
#include <cuda_runtime.h>
#include <cuda_fp16.h>
#include <math.h>
#include <stdint.h>

// Problem constants: B=2, T=2048, C=1024, H=16, D=64
#define TB   2
#define TT   2048
#define TC   1024
#define TH   16
#define TD   64
#define TM_  (TB*TT)          // 4096 rows total
#define C3   (3*TC)           // 3072
#define C4   (4*TC)           // 4096

// ---------------------------------------------------------------------------
// Scratch (no allocations allowed -> __device__ globals)
// ---------------------------------------------------------------------------
__device__ __half g_h1  [TM_ * TC];       // ln1(x)            fp16
__device__ float  g_qkv [TM_ * C3];       // qkv               fp32 (logit precision)
__device__ __half g_att [TM_ * TC];       // attention output  fp16
__device__ float  g_x1  [TM_ * TC];       // x + attn_proj     fp32
__device__ __half g_h2  [TM_ * TC];       // ln2(x1)           fp16
__device__ __half g_fc  [TM_ * C4];       // gelu(fc)          fp16
// transposed weights (K-major, [N][K], fp16)
__device__ __half g_wqkvT[C3 * TC];
__device__ __half g_wapT [TC * TC];
__device__ __half g_wfcT [C4 * TC];
__device__ __half g_woutT[TC * C4];

// ---------------------------------------------------------------------------
// Helpers
// ---------------------------------------------------------------------------
__device__ __forceinline__ float tf32r(float f) {
    uint32_t r;
    asm("cvt.rna.tf32.f32 %0, %1;" : "=r"(r) : "f"(f));
    return __uint_as_float(r);
}
__device__ __forceinline__ uint32_t smem_u32(const void* p) {
    uint32_t a;
    asm("{ .reg .u64 t; cvta.to.shared.u64 t, %1; cvt.u32.u64 %0, t; }"
        : "=r"(a) : "l"(p));
    return a;
}
__device__ __forceinline__ void cp_async16(uint32_t dst, const void* src) {
    asm volatile("cp.async.cg.shared.global [%0], [%1], 16;"
                 :: "r"(dst), "l"(src) : "memory");
}
#define CP_COMMIT() asm volatile("cp.async.commit_group;" ::: "memory")
#define CP_WAIT1()  asm volatile("cp.async.wait_group 1;" ::: "memory")

__device__ __forceinline__ void mma_tf32(float* d, const uint32_t* a, uint32_t b0, uint32_t b1) {
    asm volatile(
        "mma.sync.aligned.m16n8k8.row.col.f32.tf32.tf32.f32 "
        "{%0,%1,%2,%3}, {%4,%5,%6,%7}, {%8,%9}, {%0,%1,%2,%3};"
        : "+f"(d[0]), "+f"(d[1]), "+f"(d[2]), "+f"(d[3])
        : "r"(a[0]), "r"(a[1]), "r"(a[2]), "r"(a[3]), "r"(b0), "r"(b1));
}
__device__ __forceinline__ void mma_f16(float* d, const uint32_t* a, const uint32_t* b) {
    asm volatile(
        "mma.sync.aligned.m16n8k16.row.col.f32.f16.f16.f32 "
        "{%0,%1,%2,%3}, {%4,%5,%6,%7}, {%8,%9}, {%0,%1,%2,%3};"
        : "+f"(d[0]), "+f"(d[1]), "+f"(d[2]), "+f"(d[3])
        : "r"(a[0]), "r"(a[1]), "r"(a[2]), "r"(a[3]), "r"(b[0]), "r"(b[1]));
}
__device__ __forceinline__ void ldsm_x4(uint32_t* r, uint32_t addr) {
    asm volatile("ldmatrix.sync.aligned.m8n8.x4.shared.b16 {%0,%1,%2,%3}, [%4];"
                 : "=r"(r[0]), "=r"(r[1]), "=r"(r[2]), "=r"(r[3]) : "r"(addr));
}
__device__ __forceinline__ void ldsm_x2(uint32_t* r, uint32_t addr) {
    asm volatile("ldmatrix.sync.aligned.m8n8.x2.shared.b16 {%0,%1}, [%2];"
                 : "=r"(r[0]), "=r"(r[1]) : "r"(addr));
}

// ---------------------------------------------------------------------------
// Weight transpose + fp16 round: Wt[n][k] = half(W[k][n])
// ---------------------------------------------------------------------------
__global__ __launch_bounds__(256) void transpose_kernel(
    const float* __restrict__ W, __half* __restrict__ Wt, int K, int N)
{
    __shared__ float tile[32][33];
    int k0 = blockIdx.y * 32, n0 = blockIdx.x * 32;
    int tx = threadIdx.x, ty = threadIdx.y;   // block (32,8)
    #pragma unroll
    for (int i = ty; i < 32; i += 8)
        tile[i][tx] = W[(size_t)(k0 + i) * N + n0 + tx];
    __syncthreads();
    #pragma unroll
    for (int i = ty; i < 32; i += 8)
        Wt[(size_t)(n0 + i) * K + k0 + tx] = __float2half_rn(tile[tx][i]);
}

// ---------------------------------------------------------------------------
// fp16 tensor GEMM: C[M,N] = A[M,K] @ Bt[N,K]^T + bias (+GELU / +residual)
// BM=BN=128, BK=64. 256 threads = 8 warps (4m x 2n); warp tile 32x64.
// mma.m16n8k16 f16->f32, fragments via ldmatrix, 3-stage cp.async pipeline.
// SMEM row stride 72 halfs (144B): ldmatrix rows land on distinct 16B banks.
// EPI: 0 = bias (float out), 1 = bias+GELU (half out), 2 = bias+residual (float out)
// ---------------------------------------------------------------------------
#define GSTRIDE  72
#define GBUF_H   (128 * GSTRIDE)       // halfs per matrix per stage
#define GSTAGE_H (2 * GBUF_H)
#define GNST     3
#define G_SMEM   (GNST * GSTAGE_H * 2)   // 110592 bytes

template <int EPI, typename OutT>
__global__ __launch_bounds__(256) void hgemm(
    const __half* __restrict__ A, const __half* __restrict__ Bt,
    const float* __restrict__ bias, const float* __restrict__ res,
    OutT* __restrict__ C, int M, int N, int K)
{
    extern __shared__ __half shh[];
    uint32_t sbase = smem_u32(shh);

    int tid  = threadIdx.x;
    int wid  = tid >> 5;
    int lane = tid & 31;
    int g    = lane >> 2;
    int t    = lane & 3;
    int brow = blockIdx.y * 128;
    int bcol = blockIdx.x * 128;
    int m0   = (wid >> 1) * 32;
    int n0   = (wid & 1) * 64;

    const __half* Ag = A  + (size_t)brow * K;
    const __half* Bg = Bt + (size_t)bcol * K;

    int NC = K >> 6;   // chunks of 64

    auto issue = [&](int kc) {
        if (kc < NC) {
            int k0 = kc << 6;
            uint32_t buf = sbase + (uint32_t)(kc % GNST) * (GSTAGE_H * 2);
            #pragma unroll
            for (int i = 0; i < 4; i++) {
                int idx = tid + (i << 8);     // 0..1023
                int row = idx >> 3;
                int c   = idx & 7;
                uint32_t so = (uint32_t)(row * 144 + c * 16);
                cp_async16(buf + so,              Ag + (size_t)row * K + k0 + c * 8);
                cp_async16(buf + GBUF_H * 2 + so, Bg + (size_t)row * K + k0 + c * 8);
            }
        }
        CP_COMMIT();
    };

    float acc[2][8][4];
    #pragma unroll
    for (int i = 0; i < 2; i++)
        #pragma unroll
        for (int j = 0; j < 8; j++)
            #pragma unroll
            for (int q = 0; q < 4; q++) acc[i][j][q] = 0.f;

    issue(0);
    issue(1);

    // ldmatrix lane-address components
    int a_r = lane & 15;            // row within m16
    int a_c = (lane >> 4) * 16;     // 0 or 16 bytes (k halves)
    int b_r = lane & 7;             // row within n8
    int b_c = ((lane >> 3) & 1) * 16;

    for (int kc = 0; kc < NC; kc++) {
        CP_WAIT1();
        __syncthreads();
        issue(kc + 2);

        uint32_t As = sbase + (uint32_t)(kc % GNST) * (GSTAGE_H * 2);
        uint32_t Bs = As + GBUF_H * 2;

        #pragma unroll
        for (int ks = 0; ks < 4; ks++) {
            uint32_t a[2][4];
            #pragma unroll
            for (int i = 0; i < 2; i++)
                ldsm_x4(a[i], As + (uint32_t)((m0 + i * 16 + a_r) * 144 + ks * 32 + a_c));
            uint32_t b[8][2];
            #pragma unroll
            for (int j = 0; j < 8; j++)
                ldsm_x2(b[j], Bs + (uint32_t)((n0 + j * 8 + b_r) * 144 + ks * 32 + b_c));
            #pragma unroll
            for (int i = 0; i < 2; i++)
                #pragma unroll
                for (int j = 0; j < 8; j++)
                    mma_f16(acc[i][j], a[i], b[j]);
        }
    }

    // ---- epilogue ----
    #pragma unroll
    for (int i = 0; i < 2; i++) {
        int r0 = brow + m0 + i * 16 + g;
        int r1 = r0 + 8;
        #pragma unroll
        for (int j = 0; j < 8; j++) {
            int c0 = bcol + n0 + j * 8 + 2 * t;
            float bx = bias[c0], by = bias[c0 + 1];
            float v0 = acc[i][j][0] + bx;
            float v1 = acc[i][j][1] + by;
            float v2 = acc[i][j][2] + bx;
            float v3 = acc[i][j][3] + by;
            if (EPI == 1) {
                v0 = 0.5f * v0 * (1.0f + erff(v0 * 0.70710678118654752440f));
                v1 = 0.5f * v1 * (1.0f + erff(v1 * 0.70710678118654752440f));
                v2 = 0.5f * v2 * (1.0f + erff(v2 * 0.70710678118654752440f));
                v3 = 0.5f * v3 * (1.0f + erff(v3 * 0.70710678118654752440f));
            } else if (EPI == 2) {
                const float2 ra = *reinterpret_cast<const float2*>(res + (size_t)r0 * N + c0);
                const float2 rb = *reinterpret_cast<const float2*>(res + (size_t)r1 * N + c0);
                v0 += ra.x; v1 += ra.y; v2 += rb.x; v3 += rb.y;
            }
            if constexpr (sizeof(OutT) == 2) {
                *reinterpret_cast<__half2*>((__half*)C + (size_t)r0 * N + c0) = __floats2half2_rn(v0, v1);
                *reinterpret_cast<__half2*>((__half*)C + (size_t)r1 * N + c0) = __floats2half2_rn(v2, v3);
            } else {
                *reinterpret_cast<float2*>((float*)C + (size_t)r0 * N + c0) = make_float2(v0, v1);
                *reinterpret_cast<float2*>((float*)C + (size_t)r1 * N + c0) = make_float2(v2, v3);
            }
        }
    }
}

// ---------------------------------------------------------------------------
// Block reduce (for LayerNorm)
// ---------------------------------------------------------------------------
__device__ __forceinline__ float blockReduceSum(float v) {
    __shared__ float sh[32];
    int lane = threadIdx.x & 31;
    #pragma unroll
    for (int o = 16; o > 0; o >>= 1) v += __shfl_xor_sync(0xffffffffu, v, o);
    __syncthreads();
    if (lane == 0) sh[threadIdx.x >> 5] = v;
    __syncthreads();
    float t = (lane < 8) ? sh[lane] : 0.f;
    #pragma unroll
    for (int o = 4; o > 0; o >>= 1) t += __shfl_xor_sync(0xffffffffu, t, o);
    return __shfl_sync(0xffffffffu, t, 0);
}

// ---------------------------------------------------------------------------
// LayerNorm -> fp16 (always consumed as GEMM A operand)
// ---------------------------------------------------------------------------
__global__ __launch_bounds__(256) void layernorm_kernel(
    const float* __restrict__ x, const float* __restrict__ g,
    const float* __restrict__ b, __half* __restrict__ out)
{
    int row = blockIdx.x;
    const float4* xr = reinterpret_cast<const float4*>(x + (size_t)row * TC);
    float4 v = xr[threadIdx.x];
    float mean = blockReduceSum(v.x + v.y + v.z + v.w) * (1.f / TC);
    float dx = v.x - mean, dy = v.y - mean, dz = v.z - mean, dw = v.w - mean;
    float var = blockReduceSum(dx*dx + dy*dy + dz*dz + dw*dw) * (1.f / TC);
    float rstd = rsqrtf(var + 1e-5f);
    float4 gv = reinterpret_cast<const float4*>(g)[threadIdx.x];
    float4 bv = reinterpret_cast<const float4*>(b)[threadIdx.x];
    __half2* o2 = reinterpret_cast<__half2*>(out + (size_t)row * TC);
    o2[2 * threadIdx.x]     = __floats2half2_rn(dx * rstd * gv.x + bv.x, dy * rstd * gv.y + bv.y);
    o2[2 * threadIdx.x + 1] = __floats2half2_rn(dz * rstd * gv.z + bv.z, dw * rstd * gv.w + bv.w);
}

// ---------------------------------------------------------------------------
// Causal flash attention on tensor cores (tf32 mma, fp32 softmax).
// Grid (T/64, B*H), block 128 = 4 warps; warp w owns q-rows [16w, 16w+16).
// smem: Qs (reused as Ps) / Ks / Vs, each [64][68] fp32 (52224 B dynamic).
// S = Q@K^T and O += P@V via m16n8k8 tf32; P re-shaped via smem round-trip.
// ---------------------------------------------------------------------------
#define ASTR 68
#define A_SMEM (3 * 64 * ASTR * 4)

__global__ __launch_bounds__(128) void attn_kernel(
    const float* __restrict__ qkv, __half* __restrict__ out)
{
    extern __shared__ float sm[];
    float* Qs = sm;                 // doubles as Ps after Q frag extraction
    float* Ks = sm + 64 * ASTR;
    float* Vs = sm + 2 * 64 * ASTR;

    int qt = blockIdx.x;
    int b  = blockIdx.y >> 4;
    int h  = blockIdx.y & 15;
    int tid = threadIdx.x;
    int wid = tid >> 5;
    int lane = tid & 31;
    int g = lane >> 2;
    int t = lane & 3;
    int qr = wid * 16;

    // ---- stage Q (scaled by C^-0.5, tf32-rounded) ----
    const float* qbase = qkv + ((size_t)(b * TT + qt * 64)) * C3 + h * TD;
    #pragma unroll
    for (int i = 0; i < 8; i++) {
        int idx = tid + (i << 7);       // 0..1023
        int r = idx >> 4, c4 = idx & 15;
        float4 v = *reinterpret_cast<const float4*>(qbase + (size_t)r * C3 + c4 * 4);
        float4 w;
        w.x = tf32r(v.x * 0.03125f); w.y = tf32r(v.y * 0.03125f);
        w.z = tf32r(v.z * 0.03125f); w.w = tf32r(v.w * 0.03125f);
        *reinterpret_cast<float4*>(Qs + r * ASTR + c4 * 4) = w;
    }
    __syncthreads();

    // ---- Q a-fragments (8 k-steps x 4 regs) ----
    uint32_t Qa[8][4];
    #pragma unroll
    for (int ks = 0; ks < 8; ks++) {
        Qa[ks][0] = __float_as_uint(Qs[(qr + g)     * ASTR + ks * 8 + t]);
        Qa[ks][1] = __float_as_uint(Qs[(qr + g + 8) * ASTR + ks * 8 + t]);
        Qa[ks][2] = __float_as_uint(Qs[(qr + g)     * ASTR + ks * 8 + t + 4]);
        Qa[ks][3] = __float_as_uint(Qs[(qr + g + 8) * ASTR + ks * 8 + t + 4]);
    }

    float O[8][4];
    #pragma unroll
    for (int j = 0; j < 8; j++)
        #pragma unroll
        for (int q = 0; q < 4; q++) O[j][q] = 0.f;
    float mrow[2] = {-1e30f, -1e30f};
    float lrow[2] = {0.f, 0.f};

    for (int kt = 0; kt <= qt; kt++) {
        __syncthreads();    // protects Ks/Vs (and Ps/Qs) reuse
        const float* kbase = qkv + ((size_t)(b * TT + kt * 64)) * C3 + TC + h * TD;
        const float* vbase = kbase + TC;
        #pragma unroll
        for (int i = 0; i < 8; i++) {
            int idx = tid + (i << 7);
            int r = idx >> 4, c4 = idx & 15;
            float4 kv = *reinterpret_cast<const float4*>(kbase + (size_t)r * C3 + c4 * 4);
            float4 vv = *reinterpret_cast<const float4*>(vbase + (size_t)r * C3 + c4 * 4);
            float4 kw, vw;
            kw.x = tf32r(kv.x); kw.y = tf32r(kv.y); kw.z = tf32r(kv.z); kw.w = tf32r(kv.w);
            vw.x = tf32r(vv.x); vw.y = tf32r(vv.y); vw.z = tf32r(vv.z); vw.w = tf32r(vv.w);
            *reinterpret_cast<float4*>(Ks + r * ASTR + c4 * 4) = kw;
            *reinterpret_cast<float4*>(Vs + r * ASTR + c4 * 4) = vw;
        }
        __syncthreads();

        // ---- S = Q @ K^T ----
        float S[8][4];
        #pragma unroll
        for (int j = 0; j < 8; j++) {
            S[j][0] = S[j][1] = S[j][2] = S[j][3] = 0.f;
            #pragma unroll
            for (int ks = 0; ks < 8; ks++) {
                uint32_t b0 = __float_as_uint(Ks[(8 * j + g) * ASTR + ks * 8 + t]);
                uint32_t b1 = __float_as_uint(Ks[(8 * j + g) * ASTR + ks * 8 + t + 4]);
                mma_tf32(S[j], Qa[ks], b0, b1);
            }
        }

        // ---- causal mask (diagonal tile only) ----
        if (kt == qt) {
            int r0 = qr + g, r1 = r0 + 8;
            #pragma unroll
            for (int j = 0; j < 8; j++) {
                int c0 = 8 * j + 2 * t, c1 = c0 + 1;
                if (c0 > r0) S[j][0] = -1e30f;
                if (c1 > r0) S[j][1] = -1e30f;
                if (c0 > r1) S[j][2] = -1e30f;
                if (c1 > r1) S[j][3] = -1e30f;
            }
        }

        // ---- online softmax ----
        float mx0 = -1e30f, mx1 = -1e30f;
        #pragma unroll
        for (int j = 0; j < 8; j++) {
            mx0 = fmaxf(mx0, fmaxf(S[j][0], S[j][1]));
            mx1 = fmaxf(mx1, fmaxf(S[j][2], S[j][3]));
        }
        #pragma unroll
        for (int o = 1; o <= 2; o <<= 1) {
            mx0 = fmaxf(mx0, __shfl_xor_sync(0xffffffffu, mx0, o));
            mx1 = fmaxf(mx1, __shfl_xor_sync(0xffffffffu, mx1, o));
        }
        float mn0 = fmaxf(mrow[0], mx0);
        float mn1 = fmaxf(mrow[1], mx1);
        float cr0 = __expf(mrow[0] - mn0);
        float cr1 = __expf(mrow[1] - mn1);
        lrow[0] *= cr0; lrow[1] *= cr1;
        mrow[0] = mn0;  mrow[1] = mn1;
        #pragma unroll
        for (int j = 0; j < 8; j++) {
            O[j][0] *= cr0; O[j][1] *= cr0; O[j][2] *= cr1; O[j][3] *= cr1;
        }

        float ps0 = 0.f, ps1 = 0.f;
        #pragma unroll
        for (int j = 0; j < 8; j++) {
            float p0 = __expf(S[j][0] - mn0);
            float p1 = __expf(S[j][1] - mn0);
            float p2 = __expf(S[j][2] - mn1);
            float p3 = __expf(S[j][3] - mn1);
            ps0 += p0 + p1; ps1 += p2 + p3;
            int c = 8 * j + 2 * t;
            Qs[(qr + g)     * ASTR + c]     = tf32r(p0);
            Qs[(qr + g)     * ASTR + c + 1] = tf32r(p1);
            Qs[(qr + g + 8) * ASTR + c]     = tf32r(p2);
            Qs[(qr + g + 8) * ASTR + c + 1] = tf32r(p3);
        }
        lrow[0] += ps0; lrow[1] += ps1;
        __syncwarp();

        // ---- O += P @ V ----
        uint32_t Pa[8][4];
        #pragma unroll
        for (int ks = 0; ks < 8; ks++) {
            Pa[ks][0] = __float_as_uint(Qs[(qr + g)     * ASTR + ks * 8 + t]);
            Pa[ks][1] = __float_as_uint(Qs[(qr + g + 8) * ASTR + ks * 8 + t]);
            Pa[ks][2] = __float_as_uint(Qs[(qr + g)     * ASTR + ks * 8 + t + 4]);
            Pa[ks][3] = __float_as_uint(Qs[(qr + g + 8) * ASTR + ks * 8 + t + 4]);
        }
        #pragma unroll
        for (int j = 0; j < 8; j++) {
            #pragma unroll
            for (int ks = 0; ks < 8; ks++) {
                uint32_t b0 = __float_as_uint(Vs[(ks * 8 + t)     * ASTR + 8 * j + g]);
                uint32_t b1 = __float_as_uint(Vs[(ks * 8 + t + 4) * ASTR + 8 * j + g]);
                mma_tf32(O[j], Pa[ks], b0, b1);
            }
        }
    }

    // ---- finalize ----
    float l0 = lrow[0], l1 = lrow[1];
    #pragma unroll
    for (int o = 1; o <= 2; o <<= 1) {
        l0 += __shfl_xor_sync(0xffffffffu, l0, o);
        l1 += __shfl_xor_sync(0xffffffffu, l1, o);
    }
    float inv0 = 1.f / l0, inv1 = 1.f / l1;
    int r0 = qt * 64 + qr + g;
    int r1 = r0 + 8;
    #pragma unroll
    for (int j = 0; j < 8; j++) {
        int c = h * TD + 8 * j + 2 * t;
        *reinterpret_cast<__half2*>(out + (size_t)(b * TT + r0) * TC + c) =
            __floats2half2_rn(O[j][0] * inv0, O[j][1] * inv0);
        *reinterpret_cast<__half2*>(out + (size_t)(b * TT + r1) * TC + c) =
            __floats2half2_rn(O[j][2] * inv1, O[j][3] * inv1);
    }
}

// ---------------------------------------------------------------------------
// Launch
// ---------------------------------------------------------------------------
extern "C" void kernel_launch(void* const* d_in, const int* in_sizes, int n_in,
                              void* d_out, int out_size)
{
    const float* x           = (const float*)d_in[0];
    const float* ln1_g       = (const float*)d_in[1];
    const float* ln1_b       = (const float*)d_in[2];
    const float* w_qkv       = (const float*)d_in[3];
    const float* b_qkv       = (const float*)d_in[4];
    const float* w_attn_proj = (const float*)d_in[5];
    const float* b_attn_proj = (const float*)d_in[6];
    const float* ln2_g       = (const float*)d_in[7];
    const float* ln2_b       = (const float*)d_in[8];
    const float* w_fc        = (const float*)d_in[9];
    const float* b_fc        = (const float*)d_in[10];
    const float* w_out       = (const float*)d_in[11];
    const float* b_out       = (const float*)d_in[12];

    __half *h1, *att, *h2, *fc, *wqkvT, *wapT, *wfcT, *woutT;
    float *qkv, *x1;
    cudaGetSymbolAddress((void**)&h1,    g_h1);
    cudaGetSymbolAddress((void**)&qkv,   g_qkv);
    cudaGetSymbolAddress((void**)&att,   g_att);
    cudaGetSymbolAddress((void**)&x1,    g_x1);
    cudaGetSymbolAddress((void**)&h2,    g_h2);
    cudaGetSymbolAddress((void**)&fc,    g_fc);
    cudaGetSymbolAddress((void**)&wqkvT, g_wqkvT);
    cudaGetSymbolAddress((void**)&wapT,  g_wapT);
    cudaGetSymbolAddress((void**)&wfcT,  g_wfcT);
    cudaGetSymbolAddress((void**)&woutT, g_woutT);

    cudaFuncSetAttribute(hgemm<0, float>,  cudaFuncAttributeMaxDynamicSharedMemorySize, G_SMEM);
    cudaFuncSetAttribute(hgemm<1, __half>, cudaFuncAttributeMaxDynamicSharedMemorySize, G_SMEM);
    cudaFuncSetAttribute(hgemm<2, float>,  cudaFuncAttributeMaxDynamicSharedMemorySize, G_SMEM);
    cudaFuncSetAttribute(attn_kernel,      cudaFuncAttributeMaxDynamicSharedMemorySize, A_SMEM);

    // 0) transpose + fp16-round weights to K-major
    transpose_kernel<<<dim3(C3 / 32, TC / 32), dim3(32, 8)>>>(w_qkv,       wqkvT, TC, C3);
    transpose_kernel<<<dim3(TC / 32, TC / 32), dim3(32, 8)>>>(w_attn_proj, wapT,  TC, TC);
    transpose_kernel<<<dim3(C4 / 32, TC / 32), dim3(32, 8)>>>(w_fc,        wfcT,  TC, C4);
    transpose_kernel<<<dim3(TC / 32, C4 / 32), dim3(32, 8)>>>(w_out,       woutT, C4, TC);

    // 1) ln1(x) -> fp16
    layernorm_kernel<<<TM_, 256>>>(x, ln1_g, ln1_b, h1);
    // 2) qkv = h1 @ w_qkv + b_qkv           [4096,3072] K=1024, fp32 out
    hgemm<0, float><<<dim3(C3 / 128, TM_ / 128), 256, G_SMEM>>>(
        h1, wqkvT, b_qkv, nullptr, qkv, TM_, C3, TC);
    // 3) causal attention (tf32 tensor) -> fp16
    attn_kernel<<<dim3(TT / 64, TB * TH), 128, A_SMEM>>>(qkv, att);
    // 4) x1 = x + att @ w_attn_proj + b     [4096,1024] K=1024
    hgemm<2, float><<<dim3(TC / 128, TM_ / 128), 256, G_SMEM>>>(
        att, wapT, b_attn_proj, x, x1, TM_, TC, TC);
    // 5) ln2(x1) -> fp16
    layernorm_kernel<<<TM_, 256>>>(x1, ln2_g, ln2_b, h2);
    // 6) fc = gelu(h2 @ w_fc + b_fc)        [4096,4096] K=1024, fp16 out
    hgemm<1, __half><<<dim3(C4 / 128, TM_ / 128), 256, G_SMEM>>>(
        h2, wfcT, b_fc, nullptr, fc, TM_, C4, TC);
    // 7) out = x1 + fc @ w_out + b_out      [4096,1024] K=4096
    hgemm<2, float><<<dim3(TC / 128, TM_ / 128), 256, G_SMEM>>>(
        fc, woutT, b_out, x1, (float*)d_out, TM_, TC, C4);
}

// round 6
// speedup vs baseline: 7.4851x; 1.2815x over previous
#include <cuda_runtime.h>
#include <cuda_fp16.h>
#include <math.h>
#include <stdint.h>

// Problem constants: B=2, T=2048, C=1024, H=16, D=64
#define TB   2
#define TT   2048
#define TC   1024
#define TH   16
#define TD   64
#define TM_  (TB*TT)          // 4096 rows total
#define C3   (3*TC)           // 3072
#define C4   (4*TC)           // 4096
#define BH   (TB*TH)          // 32

// ---------------------------------------------------------------------------
// Scratch (no allocations allowed -> __device__ globals)
// ---------------------------------------------------------------------------
__device__ __half g_h1  [TM_ * TC];       // ln1(x)              fp16
__device__ __half g_q   [BH * TT * TD];   // Q (scaled)          fp16 head-major
__device__ __half g_k   [BH * TT * TD];   // K                   fp16 head-major
__device__ __half g_v   [BH * TT * TD];   // V                   fp16 head-major
__device__ __half g_att [TM_ * TC];       // attention output    fp16
__device__ float  g_x1  [TM_ * TC];       // x + attn_proj       fp32
__device__ __half g_h2  [TM_ * TC];       // ln2(x1)             fp16
__device__ __half g_fc  [TM_ * C4];       // gelu(fc)            fp16
// transposed weights (K-major, [N][K], fp16)
__device__ __half g_wqkvT[C3 * TC];
__device__ __half g_wapT [TC * TC];
__device__ __half g_wfcT [C4 * TC];
__device__ __half g_woutT[TC * C4];

// ---------------------------------------------------------------------------
// Helpers
// ---------------------------------------------------------------------------
__device__ __forceinline__ uint32_t h2u(__half2 h) {
    union { __half2 h; uint32_t u; } c;
    c.h = h;
    return c.u;
}
__device__ __forceinline__ uint32_t smem_u32(const void* p) {
    uint32_t a;
    asm("{ .reg .u64 t; cvta.to.shared.u64 t, %1; cvt.u32.u64 %0, t; }"
        : "=r"(a) : "l"(p));
    return a;
}
__device__ __forceinline__ void cp_async16(uint32_t dst, const void* src) {
    asm volatile("cp.async.cg.shared.global [%0], [%1], 16;"
                 :: "r"(dst), "l"(src) : "memory");
}
#define CP_COMMIT() asm volatile("cp.async.commit_group;" ::: "memory")
#define CP_WAIT1()  asm volatile("cp.async.wait_group 1;" ::: "memory")

__device__ __forceinline__ void mma_f16(float* d, const uint32_t* a, const uint32_t* b) {
    asm volatile(
        "mma.sync.aligned.m16n8k16.row.col.f32.f16.f16.f32 "
        "{%0,%1,%2,%3}, {%4,%5,%6,%7}, {%8,%9}, {%0,%1,%2,%3};"
        : "+f"(d[0]), "+f"(d[1]), "+f"(d[2]), "+f"(d[3])
        : "r"(a[0]), "r"(a[1]), "r"(a[2]), "r"(a[3]), "r"(b[0]), "r"(b[1]));
}
__device__ __forceinline__ void ldsm_x4(uint32_t* r, uint32_t addr) {
    asm volatile("ldmatrix.sync.aligned.m8n8.x4.shared.b16 {%0,%1,%2,%3}, [%4];"
                 : "=r"(r[0]), "=r"(r[1]), "=r"(r[2]), "=r"(r[3]) : "r"(addr));
}
__device__ __forceinline__ void ldsm_x2(uint32_t* r, uint32_t addr) {
    asm volatile("ldmatrix.sync.aligned.m8n8.x2.shared.b16 {%0,%1}, [%2];"
                 : "=r"(r[0]), "=r"(r[1]) : "r"(addr));
}
__device__ __forceinline__ void ldsm_x4_t(uint32_t* r, uint32_t addr) {
    asm volatile("ldmatrix.sync.aligned.m8n8.x4.trans.shared.b16 {%0,%1,%2,%3}, [%4];"
                 : "=r"(r[0]), "=r"(r[1]), "=r"(r[2]), "=r"(r[3]) : "r"(addr));
}

// ---------------------------------------------------------------------------
// Weight transpose + fp16 round: Wt[n][k] = half(W[k][n])
// ---------------------------------------------------------------------------
__global__ __launch_bounds__(256) void transpose_kernel(
    const float* __restrict__ W, __half* __restrict__ Wt, int K, int N)
{
    __shared__ float tile[32][33];
    int k0 = blockIdx.y * 32, n0 = blockIdx.x * 32;
    int tx = threadIdx.x, ty = threadIdx.y;   // block (32,8)
    #pragma unroll
    for (int i = ty; i < 32; i += 8)
        tile[i][tx] = W[(size_t)(k0 + i) * N + n0 + tx];
    __syncthreads();
    #pragma unroll
    for (int i = ty; i < 32; i += 8)
        Wt[(size_t)(n0 + i) * K + k0 + tx] = __float2half_rn(tile[tx][i]);
}

// ---------------------------------------------------------------------------
// fp16 tensor GEMM: C[M,N] = A[M,K] @ Bt[N,K]^T + bias (+ epilogue)
// BM=BN=128, BK=64. 256 threads = 8 warps (4m x 2n); warp tile 32x64.
// EPI: 0 = bias (float out), 1 = bias+GELU (half out),
//      2 = bias+residual (float out), 3 = qkv scatter to head-major fp16
// ---------------------------------------------------------------------------
#define GBUF_H   (128 * 72)
#define GSTAGE_H (2 * GBUF_H)
#define GNST     3
#define G_SMEM   (GNST * GSTAGE_H * 2)   // 110592 bytes

template <int EPI, typename OutT>
__global__ __launch_bounds__(256) void hgemm(
    const __half* __restrict__ A, const __half* __restrict__ Bt,
    const float* __restrict__ bias, const float* __restrict__ res,
    OutT* __restrict__ C,
    __half* __restrict__ qh, __half* __restrict__ kh, __half* __restrict__ vh,
    int M, int N, int K)
{
    extern __shared__ __half shh[];
    uint32_t sbase = smem_u32(shh);

    int tid  = threadIdx.x;
    int wid  = tid >> 5;
    int lane = tid & 31;
    int g    = lane >> 2;
    int t    = lane & 3;
    int brow = blockIdx.y * 128;
    int bcol = blockIdx.x * 128;
    int m0   = (wid >> 1) * 32;
    int n0   = (wid & 1) * 64;

    const __half* Ag = A  + (size_t)brow * K;
    const __half* Bg = Bt + (size_t)bcol * K;

    int NC = K >> 6;

    auto issue = [&](int kc) {
        if (kc < NC) {
            int k0 = kc << 6;
            uint32_t buf = sbase + (uint32_t)(kc % GNST) * (GSTAGE_H * 2);
            #pragma unroll
            for (int i = 0; i < 4; i++) {
                int idx = tid + (i << 8);
                int row = idx >> 3;
                int c   = idx & 7;
                uint32_t so = (uint32_t)(row * 144 + c * 16);
                cp_async16(buf + so,              Ag + (size_t)row * K + k0 + c * 8);
                cp_async16(buf + GBUF_H * 2 + so, Bg + (size_t)row * K + k0 + c * 8);
            }
        }
        CP_COMMIT();
    };

    float acc[2][8][4];
    #pragma unroll
    for (int i = 0; i < 2; i++)
        #pragma unroll
        for (int j = 0; j < 8; j++)
            #pragma unroll
            for (int q = 0; q < 4; q++) acc[i][j][q] = 0.f;

    issue(0);
    issue(1);

    int a_r = lane & 15;
    int a_c = (lane >> 4) * 16;
    int b_r = lane & 7;
    int b_c = ((lane >> 3) & 1) * 16;

    for (int kc = 0; kc < NC; kc++) {
        CP_WAIT1();
        __syncthreads();
        issue(kc + 2);

        uint32_t As = sbase + (uint32_t)(kc % GNST) * (GSTAGE_H * 2);
        uint32_t Bs = As + GBUF_H * 2;

        #pragma unroll
        for (int ks = 0; ks < 4; ks++) {
            uint32_t a[2][4];
            #pragma unroll
            for (int i = 0; i < 2; i++)
                ldsm_x4(a[i], As + (uint32_t)((m0 + i * 16 + a_r) * 144 + ks * 32 + a_c));
            uint32_t b[8][2];
            #pragma unroll
            for (int j = 0; j < 8; j++)
                ldsm_x2(b[j], Bs + (uint32_t)((n0 + j * 8 + b_r) * 144 + ks * 32 + b_c));
            #pragma unroll
            for (int i = 0; i < 2; i++)
                #pragma unroll
                for (int j = 0; j < 8; j++)
                    mma_f16(acc[i][j], a[i], b[j]);
        }
    }

    // ---- epilogue ----
    #pragma unroll
    for (int i = 0; i < 2; i++) {
        int r0 = brow + m0 + i * 16 + g;
        int r1 = r0 + 8;
        #pragma unroll
        for (int j = 0; j < 8; j++) {
            int c0 = bcol + n0 + j * 8 + 2 * t;
            float bx = bias[c0], by = bias[c0 + 1];
            float v0 = acc[i][j][0] + bx;
            float v1 = acc[i][j][1] + by;
            float v2 = acc[i][j][2] + bx;
            float v3 = acc[i][j][3] + by;
            if (EPI == 1) {
                v0 = 0.5f * v0 * (1.0f + erff(v0 * 0.70710678118654752440f));
                v1 = 0.5f * v1 * (1.0f + erff(v1 * 0.70710678118654752440f));
                v2 = 0.5f * v2 * (1.0f + erff(v2 * 0.70710678118654752440f));
                v3 = 0.5f * v3 * (1.0f + erff(v3 * 0.70710678118654752440f));
            } else if (EPI == 2) {
                const float2 ra = *reinterpret_cast<const float2*>(res + (size_t)r0 * N + c0);
                const float2 rb = *reinterpret_cast<const float2*>(res + (size_t)r1 * N + c0);
                v0 += ra.x; v1 += ra.y; v2 += rb.x; v3 += rb.y;
            }
            if (EPI == 3) {
                // scatter into head-major Q/K/V (Q scaled by C^-0.5 = 2^-5)
                int which = c0 >> 10;
                int cc = c0 & 1023;
                int hh = cc >> 6, d = cc & 63;
                __half* base = (which == 0) ? qh : ((which == 1) ? kh : vh);
                float s = (which == 0) ? 0.03125f : 1.0f;
                int b0i = r0 >> 11, t0i = r0 & 2047;
                int b1i = r1 >> 11, t1i = r1 & 2047;
                *reinterpret_cast<__half2*>(base + ((size_t)((b0i * TH + hh) * TT + t0i) * TD + d)) =
                    __floats2half2_rn(v0 * s, v1 * s);
                *reinterpret_cast<__half2*>(base + ((size_t)((b1i * TH + hh) * TT + t1i) * TD + d)) =
                    __floats2half2_rn(v2 * s, v3 * s);
            } else if constexpr (sizeof(OutT) == 2) {
                *reinterpret_cast<__half2*>((__half*)C + (size_t)r0 * N + c0) = __floats2half2_rn(v0, v1);
                *reinterpret_cast<__half2*>((__half*)C + (size_t)r1 * N + c0) = __floats2half2_rn(v2, v3);
            } else {
                *reinterpret_cast<float2*>((float*)C + (size_t)r0 * N + c0) = make_float2(v0, v1);
                *reinterpret_cast<float2*>((float*)C + (size_t)r1 * N + c0) = make_float2(v2, v3);
            }
        }
    }
}

// ---------------------------------------------------------------------------
// Block reduce (for LayerNorm)
// ---------------------------------------------------------------------------
__device__ __forceinline__ float blockReduceSum(float v) {
    __shared__ float sh[32];
    int lane = threadIdx.x & 31;
    #pragma unroll
    for (int o = 16; o > 0; o >>= 1) v += __shfl_xor_sync(0xffffffffu, v, o);
    __syncthreads();
    if (lane == 0) sh[threadIdx.x >> 5] = v;
    __syncthreads();
    float t = (lane < 8) ? sh[lane] : 0.f;
    #pragma unroll
    for (int o = 4; o > 0; o >>= 1) t += __shfl_xor_sync(0xffffffffu, t, o);
    return __shfl_sync(0xffffffffu, t, 0);
}

// ---------------------------------------------------------------------------
// LayerNorm -> fp16
// ---------------------------------------------------------------------------
__global__ __launch_bounds__(256) void layernorm_kernel(
    const float* __restrict__ x, const float* __restrict__ g,
    const float* __restrict__ b, __half* __restrict__ out)
{
    int row = blockIdx.x;
    const float4* xr = reinterpret_cast<const float4*>(x + (size_t)row * TC);
    float4 v = xr[threadIdx.x];
    float mean = blockReduceSum(v.x + v.y + v.z + v.w) * (1.f / TC);
    float dx = v.x - mean, dy = v.y - mean, dz = v.z - mean, dw = v.w - mean;
    float var = blockReduceSum(dx*dx + dy*dy + dz*dz + dw*dw) * (1.f / TC);
    float rstd = rsqrtf(var + 1e-5f);
    float4 gv = reinterpret_cast<const float4*>(g)[threadIdx.x];
    float4 bv = reinterpret_cast<const float4*>(b)[threadIdx.x];
    __half2* o2 = reinterpret_cast<__half2*>(out + (size_t)row * TC);
    o2[2 * threadIdx.x]     = __floats2half2_rn(dx * rstd * gv.x + bv.x, dy * rstd * gv.y + bv.y);
    o2[2 * threadIdx.x + 1] = __floats2half2_rn(dz * rstd * gv.z + bv.z, dw * rstd * gv.w + bv.w);
}

// ---------------------------------------------------------------------------
// Causal flash attention, fp16 tensor cores (m16n8k16), fp32 softmax.
// Grid (T/64, B*H), block 128 = 4 warps; warp w owns q-rows [16w, 16w+16).
// Q staged once; K/V double-buffered cp.async. P built register-only from
// S C-fragments (C-frag layout == A-frag layout for paired n-tiles).
// ---------------------------------------------------------------------------
#define AST 72    // halfs per smem row (144B; conflict-free for ldmatrix)

__global__ __launch_bounds__(128) void attn_kernel(
    const __half* __restrict__ Qh, const __half* __restrict__ Kh,
    const __half* __restrict__ Vh, __half* __restrict__ out)
{
    __shared__ __half Qs[64 * AST];
    __shared__ __half Ks[2][64 * AST];
    __shared__ __half Vs[2][64 * AST];

    int qt  = blockIdx.x;
    int bh  = blockIdx.y;          // b*16 + h
    int tid = threadIdx.x;
    int wid = tid >> 5;
    int lane = tid & 31;
    int g = lane >> 2;
    int t = lane & 3;
    int qr = wid * 16;

    // ---- stage Q tile (already C^-0.5-scaled fp16) ----
    const __half* qbase = Qh + ((size_t)bh * TT + qt * 64) * TD;
    #pragma unroll
    for (int i = 0; i < 4; i++) {
        int idx = tid + (i << 7);          // 0..511
        int r = idx >> 3, c = idx & 7;
        *reinterpret_cast<uint4*>(Qs + r * AST + c * 8) =
            *reinterpret_cast<const uint4*>(qbase + r * TD + c * 8);
    }
    __syncthreads();

    uint32_t sQ = smem_u32(Qs);
    uint32_t Qa[4][4];
    #pragma unroll
    for (int ks = 0; ks < 4; ks++)
        ldsm_x4(Qa[ks], sQ + (uint32_t)((qr + (lane & 15)) * AST + ks * 16 + (lane >> 4) * 8) * 2);

    float O[8][4];
    #pragma unroll
    for (int j = 0; j < 8; j++)
        #pragma unroll
        for (int q = 0; q < 4; q++) O[j][q] = 0.f;
    float mrow[2] = {-1e30f, -1e30f};
    float lrow[2] = {0.f, 0.f};

    auto issueKV = [&](int kt) {
        if (kt <= qt) {
            const __half* kbase = Kh + ((size_t)bh * TT + kt * 64) * TD;
            const __half* vbase = Vh + ((size_t)bh * TT + kt * 64) * TD;
            uint32_t kb = smem_u32(Ks[kt & 1]);
            uint32_t vb = smem_u32(Vs[kt & 1]);
            #pragma unroll
            for (int i = 0; i < 4; i++) {
                int idx = tid + (i << 7);
                int r = idx >> 3, c = idx & 7;
                uint32_t so = (uint32_t)(r * AST + c * 8) * 2;
                cp_async16(kb + so, kbase + r * TD + c * 8);
                cp_async16(vb + so, vbase + r * TD + c * 8);
            }
        }
        CP_COMMIT();
    };

    issueKV(0);

    for (int kt = 0; kt <= qt; kt++) {
        issueKV(kt + 1);
        CP_WAIT1();
        __syncthreads();
        uint32_t sK = smem_u32(Ks[kt & 1]);
        uint32_t sV = smem_u32(Vs[kt & 1]);

        // ---- S = Q @ K^T  (8 n-tiles of 8 kv cols) ----
        float S[8][4];
        #pragma unroll
        for (int jp = 0; jp < 4; jp++) {
            #pragma unroll
            for (int q = 0; q < 4; q++) { S[2*jp][q] = 0.f; S[2*jp+1][q] = 0.f; }
            #pragma unroll
            for (int ks = 0; ks < 4; ks++) {
                uint32_t kb4[4];
                ldsm_x4(kb4, sK + (uint32_t)((jp * 16 + ((lane >> 4) & 1) * 8 + (lane & 7)) * AST
                                             + ks * 16 + ((lane >> 3) & 1) * 8) * 2);
                mma_f16(S[2*jp],     Qa[ks], kb4);
                mma_f16(S[2*jp + 1], Qa[ks], kb4 + 2);
            }
        }

        // ---- causal mask (diagonal tile) ----
        if (kt == qt) {
            int r0 = qr + g, r1 = r0 + 8;
            #pragma unroll
            for (int j = 0; j < 8; j++) {
                int c0 = 8 * j + 2 * t, c1 = c0 + 1;
                if (c0 > r0) S[j][0] = -1e30f;
                if (c1 > r0) S[j][1] = -1e30f;
                if (c0 > r1) S[j][2] = -1e30f;
                if (c1 > r1) S[j][3] = -1e30f;
            }
        }

        // ---- online softmax ----
        float mx0 = -1e30f, mx1 = -1e30f;
        #pragma unroll
        for (int j = 0; j < 8; j++) {
            mx0 = fmaxf(mx0, fmaxf(S[j][0], S[j][1]));
            mx1 = fmaxf(mx1, fmaxf(S[j][2], S[j][3]));
        }
        #pragma unroll
        for (int o = 1; o <= 2; o <<= 1) {
            mx0 = fmaxf(mx0, __shfl_xor_sync(0xffffffffu, mx0, o));
            mx1 = fmaxf(mx1, __shfl_xor_sync(0xffffffffu, mx1, o));
        }
        float mn0 = fmaxf(mrow[0], mx0);
        float mn1 = fmaxf(mrow[1], mx1);
        float cr0 = __expf(mrow[0] - mn0);
        float cr1 = __expf(mrow[1] - mn1);
        lrow[0] *= cr0; lrow[1] *= cr1;
        mrow[0] = mn0;  mrow[1] = mn1;
        #pragma unroll
        for (int j = 0; j < 8; j++) {
            O[j][0] *= cr0; O[j][1] *= cr0; O[j][2] *= cr1; O[j][3] *= cr1;
        }

        // exp + A-fragment packing (register-only; C-frag pair -> A-frag)
        uint32_t Pa[4][4];
        float ps0 = 0.f, ps1 = 0.f;
        #pragma unroll
        for (int kk = 0; kk < 4; kk++) {
            #pragma unroll
            for (int jj = 0; jj < 2; jj++) {
                int j = 2 * kk + jj;
                float p0 = __expf(S[j][0] - mn0);
                float p1 = __expf(S[j][1] - mn0);
                float p2 = __expf(S[j][2] - mn1);
                float p3 = __expf(S[j][3] - mn1);
                ps0 += p0 + p1; ps1 += p2 + p3;
                Pa[kk][2*jj]     = h2u(__floats2half2_rn(p0, p1));
                Pa[kk][2*jj + 1] = h2u(__floats2half2_rn(p2, p3));
            }
        }
        lrow[0] += ps0; lrow[1] += ps1;

        // ---- O += P @ V  (V b-frags via ldmatrix.trans) ----
        #pragma unroll
        for (int jdp = 0; jdp < 4; jdp++) {
            #pragma unroll
            for (int kk = 0; kk < 4; kk++) {
                uint32_t vb4[4];
                ldsm_x4_t(vb4, sV + (uint32_t)((kk * 16 + ((lane >> 3) & 1) * 8 + (lane & 7)) * AST
                                               + jdp * 16 + ((lane >> 4) & 1) * 8) * 2);
                mma_f16(O[2*jdp],     Pa[kk], vb4);
                mma_f16(O[2*jdp + 1], Pa[kk], vb4 + 2);
            }
        }
        __syncthreads();
    }

    // ---- finalize ----
    float l0 = lrow[0], l1 = lrow[1];
    #pragma unroll
    for (int o = 1; o <= 2; o <<= 1) {
        l0 += __shfl_xor_sync(0xffffffffu, l0, o);
        l1 += __shfl_xor_sync(0xffffffffu, l1, o);
    }
    float inv0 = 1.f / l0, inv1 = 1.f / l1;
    int b = bh >> 4, h = bh & 15;
    int r0 = qt * 64 + qr + g;
    int r1 = r0 + 8;
    #pragma unroll
    for (int j = 0; j < 8; j++) {
        int c = h * TD + 8 * j + 2 * t;
        *reinterpret_cast<__half2*>(out + (size_t)(b * TT + r0) * TC + c) =
            __floats2half2_rn(O[j][0] * inv0, O[j][1] * inv0);
        *reinterpret_cast<__half2*>(out + (size_t)(b * TT + r1) * TC + c) =
            __floats2half2_rn(O[j][2] * inv1, O[j][3] * inv1);
    }
}

// ---------------------------------------------------------------------------
// Launch
// ---------------------------------------------------------------------------
extern "C" void kernel_launch(void* const* d_in, const int* in_sizes, int n_in,
                              void* d_out, int out_size)
{
    const float* x           = (const float*)d_in[0];
    const float* ln1_g       = (const float*)d_in[1];
    const float* ln1_b       = (const float*)d_in[2];
    const float* w_qkv       = (const float*)d_in[3];
    const float* b_qkv       = (const float*)d_in[4];
    const float* w_attn_proj = (const float*)d_in[5];
    const float* b_attn_proj = (const float*)d_in[6];
    const float* ln2_g       = (const float*)d_in[7];
    const float* ln2_b       = (const float*)d_in[8];
    const float* w_fc        = (const float*)d_in[9];
    const float* b_fc        = (const float*)d_in[10];
    const float* w_out       = (const float*)d_in[11];
    const float* b_out       = (const float*)d_in[12];

    __half *h1, *qh, *kh, *vh, *att, *h2, *fc, *wqkvT, *wapT, *wfcT, *woutT;
    float *x1;
    cudaGetSymbolAddress((void**)&h1,    g_h1);
    cudaGetSymbolAddress((void**)&qh,    g_q);
    cudaGetSymbolAddress((void**)&kh,    g_k);
    cudaGetSymbolAddress((void**)&vh,    g_v);
    cudaGetSymbolAddress((void**)&att,   g_att);
    cudaGetSymbolAddress((void**)&x1,    g_x1);
    cudaGetSymbolAddress((void**)&h2,    g_h2);
    cudaGetSymbolAddress((void**)&fc,    g_fc);
    cudaGetSymbolAddress((void**)&wqkvT, g_wqkvT);
    cudaGetSymbolAddress((void**)&wapT,  g_wapT);
    cudaGetSymbolAddress((void**)&wfcT,  g_wfcT);
    cudaGetSymbolAddress((void**)&woutT, g_woutT);

    cudaFuncSetAttribute(hgemm<0, float>,  cudaFuncAttributeMaxDynamicSharedMemorySize, G_SMEM);
    cudaFuncSetAttribute(hgemm<1, __half>, cudaFuncAttributeMaxDynamicSharedMemorySize, G_SMEM);
    cudaFuncSetAttribute(hgemm<2, float>,  cudaFuncAttributeMaxDynamicSharedMemorySize, G_SMEM);
    cudaFuncSetAttribute(hgemm<3, float>,  cudaFuncAttributeMaxDynamicSharedMemorySize, G_SMEM);

    // 0) transpose + fp16-round weights to K-major
    transpose_kernel<<<dim3(C3 / 32, TC / 32), dim3(32, 8)>>>(w_qkv,       wqkvT, TC, C3);
    transpose_kernel<<<dim3(TC / 32, TC / 32), dim3(32, 8)>>>(w_attn_proj, wapT,  TC, TC);
    transpose_kernel<<<dim3(C4 / 32, TC / 32), dim3(32, 8)>>>(w_fc,        wfcT,  TC, C4);
    transpose_kernel<<<dim3(TC / 32, C4 / 32), dim3(32, 8)>>>(w_out,       woutT, C4, TC);

    // 1) ln1(x) -> fp16
    layernorm_kernel<<<TM_, 256>>>(x, ln1_g, ln1_b, h1);
    // 2) qkv GEMM, epilogue scatters Q(scaled)/K/V head-major fp16
    hgemm<3, float><<<dim3(C3 / 128, TM_ / 128), 256, G_SMEM>>>(
        h1, wqkvT, b_qkv, nullptr, (float*)nullptr, qh, kh, vh, TM_, C3, TC);
    // 3) causal flash attention (fp16 tensor) -> fp16
    attn_kernel<<<dim3(TT / 64, BH), 128>>>(qh, kh, vh, att);
    // 4) x1 = x + att @ w_attn_proj + b
    hgemm<2, float><<<dim3(TC / 128, TM_ / 128), 256, G_SMEM>>>(
        att, wapT, b_attn_proj, x, x1, nullptr, nullptr, nullptr, TM_, TC, TC);
    // 5) ln2(x1) -> fp16
    layernorm_kernel<<<TM_, 256>>>(x1, ln2_g, ln2_b, h2);
    // 6) fc = gelu(h2 @ w_fc + b_fc) -> fp16
    hgemm<1, __half><<<dim3(C4 / 128, TM_ / 128), 256, G_SMEM>>>(
        h2, wfcT, b_fc, nullptr, fc, nullptr, nullptr, nullptr, TM_, C4, TC);
    // 7) out = x1 + fc @ w_out + b_out
    hgemm<2, float><<<dim3(TC / 128, TM_ / 128), 256, G_SMEM>>>(
        fc, woutT, b_out, x1, (float*)d_out, nullptr, nullptr, nullptr, TM_, TC, C4);
}